// round 16
// baseline (speedup 1.0000x reference)
#include <cuda_runtime.h>
#include <cuda_fp16.h>
#include <cstdint>

#define HH    64
#define WW    64
#define CIN   512
#define COUT  512
#define NB    16
#define EPSF  1e-8f

// ---------------- scratch (__device__ globals) -----------------------------
__device__ __half g_xhi[(size_t)NB * HH * WW * CIN];   // [n][h][w][c]
__device__ __half g_whi[(size_t)9 * COUT * CIN];       // [t][o][c]
__device__ float  g_w2 [(size_t)CIN * COUT];           // [c][o]
__device__ float  g_d  [(size_t)NB * COUT];            // [n][o]

// ---------------- helpers --------------------------------------------------
__device__ __forceinline__ uint32_t smem_to_u32(const void* p) {
    uint32_t a;
    asm("{ .reg .u64 t; cvta.to.shared.u64 t, %1; cvt.u32.u64 %0, t; }"
        : "=r"(a) : "l"(p));
    return a;
}
__device__ __forceinline__ void cpa16(uint32_t dst, const void* src, bool ok) {
    asm volatile("cp.async.cg.shared.global [%0], [%1], 16, %2;"
                 :: "r"(dst), "l"(src), "r"(ok ? 16u : 0u) : "memory");
}
#define CP_COMMIT() asm volatile("cp.async.commit_group;" ::: "memory")
#define CP_WAIT1()  asm volatile("cp.async.wait_group 1;" ::: "memory")

#define LDSM_X4(r, addr) \
    asm volatile("ldmatrix.sync.aligned.m8n8.x4.shared.b16 {%0,%1,%2,%3}, [%4];" \
        : "=r"((r)[0]), "=r"((r)[1]), "=r"((r)[2]), "=r"((r)[3]) : "r"(addr))
#define LDSM_X2(r, addr) \
    asm volatile("ldmatrix.sync.aligned.m8n8.x2.shared.b16 {%0,%1}, [%2];" \
        : "=r"((r)[0]), "=r"((r)[1]) : "r"(addr))
#define MMA16816(c, a, b) \
    asm volatile("mma.sync.aligned.m16n8k16.row.col.f32.f16.f16.f32 " \
        "{%0,%1,%2,%3}, {%4,%5,%6,%7}, {%8,%9}, {%0,%1,%2,%3};" \
        : "+f"((c)[0]), "+f"((c)[1]), "+f"((c)[2]), "+f"((c)[3]) \
        : "r"((a)[0]), "r"((a)[1]), "r"((a)[2]), "r"((a)[3]), \
          "r"((b)[0]), "r"((b)[1]))

// ---------------------------------------------------------------------------
// prep_x: x_mod = x * s  ->  [n][h][w][c] fp16 (tiled transpose)
// ---------------------------------------------------------------------------
__global__ __launch_bounds__(256) void prep_x_kernel(const float* __restrict__ x,
                                                     const float* __restrict__ s) {
    const int cb = blockIdx.x, h = blockIdx.y, n = blockIdx.z;
    __shared__ float tile[64][65];
    const int tid = threadIdx.x;
#pragma unroll
    for (int it = 0; it < 16; ++it) {
        int idx = it * 256 + tid;
        int c = idx >> 6, wq = idx & 63;
        float sv = s[n * CIN + cb * 64 + c];
        tile[c][wq] = x[(((size_t)n * CIN + cb * 64 + c) * HH + h) * WW + wq] * sv;
    }
    __syncthreads();
#pragma unroll
    for (int it = 0; it < 8; ++it) {
        int idx = it * 256 + tid;
        int cp = idx & 31, wq = idx >> 5;
        __half h0 = __float2half_rn(tile[2 * cp][wq]);
        __half h1 = __float2half_rn(tile[2 * cp + 1][wq]);
        size_t off = (((size_t)n * HH + h) * WW + wq) * CIN + cb * 64 + 2 * cp;
        *(__half2*)(g_xhi + off) = __half2(h0, h1);
    }
}

// ---------------------------------------------------------------------------
// prep_w: w -> [t][o][c] fp16 + w2[c][o]
// ---------------------------------------------------------------------------
__global__ __launch_bounds__(256) void prep_w_kernel(const float* __restrict__ w) {
    int idx = blockIdx.x * 256 + threadIdx.x;
    if (idx >= CIN * COUT) return;
    int c = idx & 511, o = idx >> 9;
    const float* wp = w + ((size_t)o * CIN + c) * 9;
    float sum = 0.f;
#pragma unroll
    for (int t = 0; t < 9; ++t) {
        float v = wp[t];
        sum += v * v;
        g_whi[((size_t)t * COUT + o) * CIN + c] = __float2half_rn(v);
    }
    g_w2[(size_t)c * COUT + o] = sum;
}

// ---------------------------------------------------------------------------
// d_kernel
// ---------------------------------------------------------------------------
__global__ void d_kernel(const float* __restrict__ s) {
    int n = blockIdx.y;
    int o = blockIdx.x * 128 + threadIdx.x;
    __shared__ float s2[CIN];
    for (int i = threadIdx.x; i < CIN; i += 128) {
        float v = s[n * CIN + i];
        s2[i] = v * v;
    }
    __syncthreads();
    float acc = 0.f;
#pragma unroll 8
    for (int c = 0; c < CIN; ++c) acc += s2[c] * g_w2[(size_t)c * COUT + o];
    g_d[n * COUT + o] = rsqrtf(acc + EPSF);
}

// ---------------------------------------------------------------------------
// main HMMA conv kernel — single-pass fp16, tap-stationary X, 3 taps/stage,
// warp tile 64px x 64o, BATCHED fragments: one load batch per kw (K=32),
// 64 MMAs per batch -> 3 exposure events per stage instead of 6.
// CTA = (128 outs, 256 pixels = 4 rows, n); 8 warps 4x2
// X region: 6 rows x 66 cols (haloed) x 32c, double buffered (per cb)
// B buffer: 3 taps x 128 o x 32 c, 3-deep ring (per stage)
// ---------------------------------------------------------------------------
#define NT      256
#define XSL     80                     // bytes per pixel slot (32 halves + pad)
#define XROW    66                     // haloed width
#define XNSL    396                    // 6 * 66 slots
#define X_B     (XNSL * XSL)           // 31680 (one buffer)
#define AST     80                     // B: bytes per o-row
#define B_B     (128 * AST)            // 10240 (one tap)
#define BST     (3 * B_B)              // 30720 (one stage buffer)
#define SM_DYN  (1024 + 2 * X_B + 3 * BST)   // 156544

__global__ __launch_bounds__(NT, 1)
void conv_mma_kernel(const float* __restrict__ noise,
                     const float* __restrict__ bias,
                     float* __restrict__ out) {
    extern __shared__ char smem[];
    float* dd = (float*)smem;          // 128 floats
    float* bb = dd + 128;              // 128 floats
    const uint32_t xsb = smem_to_u32(smem + 1024);
    const uint32_t bsb = xsb + 2 * X_B;

    const int tid = threadIdx.x;
    const int lid = tid & 31, wid = tid >> 5;
    const int wm = wid >> 1, wn = wid & 1;       // 4 x 2 warp grid
    const int o0 = blockIdx.x * 128;
    const int by = blockIdx.y;                   // image rows 4by .. 4by+3
    const int n  = blockIdx.z;

    if (tid < 128) {
        dd[tid] = g_d[n * COUT + o0 + tid];
        bb[tid] = bias[o0 + tid];
    }

    const __half* xh = g_xhi + (size_t)n * HH * WW * CIN;

    // ldmatrix per-thread base offsets (warp wm = local image row wm)
    const uint32_t aoff = (uint32_t)((wm * XROW + (lid & 15)) * XSL
                                     + (lid >> 4) * 16);
    const uint32_t boff = (uint32_t)((wn * 64 + (lid & 7)) * AST + ((lid >> 3) & 1) * 16);

    float C[4][8][4];
#pragma unroll
    for (int i = 0; i < 4; ++i)
#pragma unroll
        for (int j = 0; j < 8; ++j)
#pragma unroll
            for (int k = 0; k < 4; ++k) C[i][j][k] = 0.f;

    // ---- X region prefetch for c-block cb_ into buffer cb_&1 ----
#define PREF_X(cb_) do {                                                         \
    uint32_t xb_ = xsb + ((cb_) & 1) * X_B;                                      \
    _Pragma("unroll")                                                            \
    for (int it = 0; it < 7; ++it) {                                             \
        int idx = it * NT + tid;                                                 \
        if (idx < XNSL * 4) {                                                    \
            int slot = idx >> 2, q = idx & 3;                                    \
            int hl = slot / XROW, wl = slot - hl * XROW;                         \
            int h_ = 4 * by + hl - 1, w_ = wl - 1;                               \
            bool ok = (h_ >= 0) & (h_ < HH) & (w_ >= 0) & (w_ < WW);             \
            int gi = ok ? ((h_ * WW + w_) * CIN + (cb_) * 32 + q * 8) : 0;       \
            cpa16(xb_ + slot * XSL + q * 16, xh + gi, ok);                       \
        }                                                                        \
    }                                                                            \
} while (0)

    // ---- B prefetch for stage st (cb = st/3, kh = st%3): 3 kw taps ----
#define PREF_B(st) do {                                                          \
    const int cb_ = (st) / 3, kh_ = (st) - cb_ * 3;                              \
    uint32_t base_ = bsb + ((st) % 3) * BST;                                     \
    _Pragma("unroll")                                                            \
    for (int it = 0; it < 6; ++it) {                                             \
        int idx = it * NT + tid;                                                 \
        int slot = idx >> 2, q = idx & 3;                                        \
        int kw_ = slot >> 7, r = slot & 127;                                     \
        const int t_ = kh_ * 3 + kw_;                                            \
        size_t wb = ((size_t)t_ * COUT + o0 + r) * CIN + cb_ * 32 + q * 8;       \
        cpa16(base_ + kw_ * B_B + r * AST + q * 16, g_whi + wb, true);           \
    }                                                                            \
} while (0)

    // prologue: 2 groups in flight
    PREF_X(0); PREF_B(0); CP_COMMIT();   // g0 (X0 + B0)
    PREF_B(1); CP_COMMIT();              // g1

#pragma unroll 1
    for (int s = 0; s < 48; ++s) {
        const int cb = s / 3;
        const int kh = s - cb * 3;

        CP_WAIT1();                      // own g(s) complete (g(s+1) may fly)
        __syncthreads();                 // cross-thread visibility + done s-1

        // prefetch 2 ahead into ring slot (s+2)%3 (disjoint from s, s+1)
        if (s + 2 < 48) PREF_B(s + 2);
        if (kh == 0 && cb + 1 < 16) PREF_X(cb + 1);
        CP_COMMIT();                     // g(s+2)

        const uint32_t abase = xsb + (cb & 1) * X_B + aoff
                               + (uint32_t)(kh * XROW * XSL);
        const uint32_t bbase = bsb + (s % 3) * BST + boff;

#pragma unroll
        for (int kw = 0; kw < 3; ++kw) {
            uint32_t bhf[2][8][2], ahf[2][4][4];
            // ---- one fused load batch for both kc halves (K=32) ----
#pragma unroll
            for (int nt = 0; nt < 8; ++nt)
                LDSM_X2(bhf[0][nt], bbase + kw * B_B + nt * (8 * AST));
#pragma unroll
            for (int mt = 0; mt < 4; ++mt)
                LDSM_X4(ahf[0][mt], abase + (kw + mt * 16) * XSL);
#pragma unroll
            for (int nt = 0; nt < 8; ++nt)
                LDSM_X2(bhf[1][nt], bbase + kw * B_B + nt * (8 * AST) + 32);
#pragma unroll
            for (int mt = 0; mt < 4; ++mt)
                LDSM_X4(ahf[1][mt], abase + (kw + mt * 16) * XSL + 32);
            // ---- 64 MMAs (kc=0 first: its frags landed earliest) ----
#pragma unroll
            for (int kc = 0; kc < 2; ++kc)
#pragma unroll
                for (int mt = 0; mt < 4; ++mt)
#pragma unroll
                    for (int nt = 0; nt < 8; ++nt)
                        MMA16816(C[mt][nt], ahf[kc][mt], bhf[kc][nt]);
        }
    }
#undef PREF_B
#undef PREF_X

    // ---- epilogue: demod, bias, noise, LeakyReLU ----
    const int h = 4 * by + wm;
#pragma unroll
    for (int mt = 0; mt < 4; ++mt)
#pragma unroll
        for (int nt = 0; nt < 8; ++nt)
#pragma unroll
            for (int i = 0; i < 4; ++i) {
                int wq = mt * 16 + (lid >> 2) + (i >> 1) * 8;
                int o  = wn * 64 + nt * 8 + (lid & 3) * 2 + (i & 1);
                size_t oa = (((size_t)n * COUT + o0 + o) * HH + h) * WW + wq;
                float v = C[mt][nt][i] * dd[o] + bb[o] + noise[oa];
                out[oa] = (v >= 0.f) ? v : 0.2f * v;
            }
}

// ---------------------------------------------------------------------------
extern "C" void kernel_launch(void* const* d_in, const int* in_sizes, int n_in,
                              void* d_out, int out_size) {
    const float* x     = (const float*)d_in[0];
    const float* s     = (const float*)d_in[1];
    const float* noise = (const float*)d_in[2];
    const float* w     = (const float*)d_in[3];
    const float* b     = (const float*)d_in[4];
    float* out = (float*)d_out;

    cudaFuncSetAttribute(conv_mma_kernel,
                         cudaFuncAttributeMaxDynamicSharedMemorySize, SM_DYN);

    prep_x_kernel<<<dim3(8, 64, 16), 256>>>(x, s);
    prep_w_kernel<<<(CIN * COUT + 255) / 256, 256>>>(w);
    d_kernel<<<dim3(COUT / 128, NB), 128>>>(s);
    conv_mma_kernel<<<dim3(COUT / 128, HH / 4, NB), NT, SM_DYN>>>(noise, b, out);
}

// round 17
// speedup vs baseline: 1.0573x; 1.0573x over previous
#include <cuda_runtime.h>
#include <cuda_fp16.h>
#include <cstdint>

#define HH    64
#define WW    64
#define CIN   512
#define COUT  512
#define NB    16
#define EPSF  1e-8f

// ---------------- scratch (__device__ globals) -----------------------------
__device__ __half g_xhi[(size_t)NB * HH * WW * CIN];   // [n][h][w][c]
__device__ __half g_whi[(size_t)9 * COUT * CIN];       // [t][o][c]
__device__ float  g_w2 [(size_t)CIN * COUT];           // [c][o]
__device__ float  g_d  [(size_t)NB * COUT];            // [n][o]

// ---------------- helpers --------------------------------------------------
__device__ __forceinline__ uint32_t smem_to_u32(const void* p) {
    uint32_t a;
    asm("{ .reg .u64 t; cvta.to.shared.u64 t, %1; cvt.u32.u64 %0, t; }"
        : "=r"(a) : "l"(p));
    return a;
}
__device__ __forceinline__ void cpa16(uint32_t dst, const void* src, bool ok) {
    asm volatile("cp.async.cg.shared.global [%0], [%1], 16, %2;"
                 :: "r"(dst), "l"(src), "r"(ok ? 16u : 0u) : "memory");
}
#define CP_COMMIT() asm volatile("cp.async.commit_group;" ::: "memory")
#define CP_WAIT0()  asm volatile("cp.async.wait_group 0;" ::: "memory")

#define LDSM_X4(r, addr) \
    asm volatile("ldmatrix.sync.aligned.m8n8.x4.shared.b16 {%0,%1,%2,%3}, [%4];" \
        : "=r"((r)[0]), "=r"((r)[1]), "=r"((r)[2]), "=r"((r)[3]) : "r"(addr))
#define LDSM_X2(r, addr) \
    asm volatile("ldmatrix.sync.aligned.m8n8.x2.shared.b16 {%0,%1}, [%2];" \
        : "=r"((r)[0]), "=r"((r)[1]) : "r"(addr))
#define MMA16816(c, a, b) \
    asm volatile("mma.sync.aligned.m16n8k16.row.col.f32.f16.f16.f32 " \
        "{%0,%1,%2,%3}, {%4,%5,%6,%7}, {%8,%9}, {%0,%1,%2,%3};" \
        : "+f"((c)[0]), "+f"((c)[1]), "+f"((c)[2]), "+f"((c)[3]) \
        : "r"((a)[0]), "r"((a)[1]), "r"((a)[2]), "r"((a)[3]), \
          "r"((b)[0]), "r"((b)[1]))

// ---------------------------------------------------------------------------
// prep_x: x_mod = x * s  ->  [n][h][w][c] fp16 (tiled transpose)
// ---------------------------------------------------------------------------
__global__ __launch_bounds__(256) void prep_x_kernel(const float* __restrict__ x,
                                                     const float* __restrict__ s) {
    const int cb = blockIdx.x, h = blockIdx.y, n = blockIdx.z;
    __shared__ float tile[64][65];
    const int tid = threadIdx.x;
#pragma unroll
    for (int it = 0; it < 16; ++it) {
        int idx = it * 256 + tid;
        int c = idx >> 6, wq = idx & 63;
        float sv = s[n * CIN + cb * 64 + c];
        tile[c][wq] = x[(((size_t)n * CIN + cb * 64 + c) * HH + h) * WW + wq] * sv;
    }
    __syncthreads();
#pragma unroll
    for (int it = 0; it < 8; ++it) {
        int idx = it * 256 + tid;
        int cp = idx & 31, wq = idx >> 5;
        __half h0 = __float2half_rn(tile[2 * cp][wq]);
        __half h1 = __float2half_rn(tile[2 * cp + 1][wq]);
        size_t off = (((size_t)n * HH + h) * WW + wq) * CIN + cb * 64 + 2 * cp;
        *(__half2*)(g_xhi + off) = __half2(h0, h1);
    }
}

// ---------------------------------------------------------------------------
// prep_w: w -> [t][o][c] fp16 + w2[c][o]
// ---------------------------------------------------------------------------
__global__ __launch_bounds__(256) void prep_w_kernel(const float* __restrict__ w) {
    int idx = blockIdx.x * 256 + threadIdx.x;
    if (idx >= CIN * COUT) return;
    int c = idx & 511, o = idx >> 9;
    const float* wp = w + ((size_t)o * CIN + c) * 9;
    float sum = 0.f;
#pragma unroll
    for (int t = 0; t < 9; ++t) {
        float v = wp[t];
        sum += v * v;
        g_whi[((size_t)t * COUT + o) * CIN + c] = __float2half_rn(v);
    }
    g_w2[(size_t)c * COUT + o] = sum;
}

// ---------------------------------------------------------------------------
// d_kernel
// ---------------------------------------------------------------------------
__global__ void d_kernel(const float* __restrict__ s) {
    int n = blockIdx.y;
    int o = blockIdx.x * 128 + threadIdx.x;
    __shared__ float s2[CIN];
    for (int i = threadIdx.x; i < CIN; i += 128) {
        float v = s[n * CIN + i];
        s2[i] = v * v;
    }
    __syncthreads();
    float acc = 0.f;
#pragma unroll 8
    for (int c = 0; c < CIN; ++c) acc += s2[c] * g_w2[(size_t)c * COUT + o];
    g_d[n * COUT + o] = rsqrtf(acc + EPSF);
}

// ---------------------------------------------------------------------------
// main HMMA conv kernel — single-pass fp16, tap-stationary X, K=64 per tap,
// 3 taps/stage, 24 stages, 72 tap-boundaries per CTA (was 144).
// CTA = (128 outs, 256 pixels = 4 rows, n); 8 warps 4x2, warp = 64px x 64o
// X region: 6 rows x 66 cols (haloed) x 64c, double buffered (per cb64)
// B buffer: 3 taps x 128 o x 64 c, double buffered (per stage)
// ---------------------------------------------------------------------------
#define NT      256
#define XSL     144                    // bytes per pixel slot (64 halves + pad)
#define XROW    66                     // haloed width
#define XNSL    396                    // 6 * 66 slots
#define X_B     (XNSL * XSL)           // 57024 (one buffer)
#define AST     144                    // B: bytes per o-row (64 halves + pad)
#define B_B     (128 * AST)            // 18432 (one tap)
#define BST     (3 * B_B)              // 55296 (one stage buffer)
#define SM_DYN  (1024 + 2 * X_B + 2 * BST)   // 225664

__global__ __launch_bounds__(NT, 1)
void conv_mma_kernel(const float* __restrict__ noise,
                     const float* __restrict__ bias,
                     float* __restrict__ out) {
    extern __shared__ char smem[];
    float* dd = (float*)smem;          // 128 floats
    float* bb = dd + 128;              // 128 floats
    const uint32_t xsb = smem_to_u32(smem + 1024);
    const uint32_t bsb = xsb + 2 * X_B;

    const int tid = threadIdx.x;
    const int lid = tid & 31, wid = tid >> 5;
    const int wm = wid >> 1, wn = wid & 1;       // 4 x 2 warp grid
    const int o0 = blockIdx.x * 128;
    const int by = blockIdx.y;                   // image rows 4by .. 4by+3
    const int n  = blockIdx.z;

    if (tid < 128) {
        dd[tid] = g_d[n * COUT + o0 + tid];
        bb[tid] = bias[o0 + tid];
    }

    const __half* xh = g_xhi + (size_t)n * HH * WW * CIN;

    // ldmatrix per-thread base offsets (warp wm = local image row wm)
    const uint32_t aoff = (uint32_t)((wm * XROW + (lid & 15)) * XSL
                                     + (lid >> 4) * 16);
    const uint32_t boff = (uint32_t)((wn * 64 + (lid & 7)) * AST + ((lid >> 3) & 1) * 16);

    float C[4][8][4];
#pragma unroll
    for (int i = 0; i < 4; ++i)
#pragma unroll
        for (int j = 0; j < 8; ++j)
#pragma unroll
            for (int k = 0; k < 4; ++k) C[i][j][k] = 0.f;

    // ---- X region prefetch for c-block-64 cb_ into buffer cb_&1 ----
    // 396 slots x 8 chunks = 3168 cp.async over 256 threads
#define PREF_X(cb_) do {                                                         \
    uint32_t xb_ = xsb + ((cb_) & 1) * X_B;                                      \
    _Pragma("unroll")                                                            \
    for (int it = 0; it < 13; ++it) {                                            \
        int idx = it * NT + tid;                                                 \
        if (idx < XNSL * 8) {                                                    \
            int slot = idx >> 3, q = idx & 7;                                    \
            int hl = slot / XROW, wl = slot - hl * XROW;                         \
            int h_ = 4 * by + hl - 1, w_ = wl - 1;                               \
            bool ok = (h_ >= 0) & (h_ < HH) & (w_ >= 0) & (w_ < WW);             \
            int gi = ok ? ((h_ * WW + w_) * CIN + (cb_) * 64 + q * 8) : 0;       \
            cpa16(xb_ + slot * XSL + q * 16, xh + gi, ok);                       \
        }                                                                        \
    }                                                                            \
} while (0)

    // ---- B prefetch for stage st (cb = st/3, kh = st%3): 3 kw taps, 64 c ----
    // 3 taps x 128 rows x 8 chunks = 3072 cp.async over 256 threads
#define PREF_B(st) do {                                                          \
    const int cb_ = (st) / 3, kh_ = (st) - cb_ * 3;                              \
    uint32_t base_ = bsb + ((st) & 1) * BST;                                     \
    _Pragma("unroll")                                                            \
    for (int it = 0; it < 12; ++it) {                                            \
        int idx = it * NT + tid;                                                 \
        int slot = idx >> 3, q = idx & 7;                                        \
        int kw_ = slot >> 7, r = slot & 127;                                     \
        const int t_ = kh_ * 3 + kw_;                                            \
        size_t wb = ((size_t)t_ * COUT + o0 + r) * CIN + cb_ * 64 + q * 8;       \
        cpa16(base_ + kw_ * B_B + r * AST + q * 16, g_whi + wb, true);           \
    }                                                                            \
} while (0)

    // prologue: stage-0 data (X cb0 + B stage0) in one group
    PREF_X(0); PREF_B(0); CP_COMMIT();

#pragma unroll 1
    for (int s = 0; s < 24; ++s) {
        const int cb = s / 3;
        const int kh = s - cb * 3;

        CP_WAIT0();                      // group committed one stage ago done
        __syncthreads();                 // all warps done reading old slots

        // prefetch next stage's B (ring slot (s+1)&1) and next X at kh==0
        if (s + 1 < 24) PREF_B(s + 1);
        if (kh == 0 && cb + 1 < 8) PREF_X(cb + 1);
        CP_COMMIT();

        const uint32_t abase = xsb + (cb & 1) * X_B + aoff
                               + (uint32_t)(kh * XROW * XSL);
        const uint32_t bbase = bsb + (s & 1) * BST + boff;

#pragma unroll
        for (int kw = 0; kw < 3; ++kw) {
#pragma unroll
            for (int kc = 0; kc < 4; ++kc) {
                uint32_t bhf[8][2];
#pragma unroll
                for (int nt = 0; nt < 8; ++nt)
                    LDSM_X2(bhf[nt], bbase + kw * B_B + nt * (8 * AST) + kc * 32);
                uint32_t ahf[4][4];
#pragma unroll
                for (int mt = 0; mt < 4; ++mt)
                    LDSM_X4(ahf[mt], abase + (kw + mt * 16) * XSL + kc * 32);
#pragma unroll
                for (int mt = 0; mt < 4; ++mt)
#pragma unroll
                    for (int nt = 0; nt < 8; ++nt)
                        MMA16816(C[mt][nt], ahf[mt], bhf[nt]);
            }
        }
    }
#undef PREF_B
#undef PREF_X

    // ---- epilogue: demod, bias, noise, LeakyReLU ----
    const int h = 4 * by + wm;
#pragma unroll
    for (int mt = 0; mt < 4; ++mt)
#pragma unroll
        for (int nt = 0; nt < 8; ++nt)
#pragma unroll
            for (int i = 0; i < 4; ++i) {
                int wq = mt * 16 + (lid >> 2) + (i >> 1) * 8;
                int o  = wn * 64 + nt * 8 + (lid & 3) * 2 + (i & 1);
                size_t oa = (((size_t)n * COUT + o0 + o) * HH + h) * WW + wq;
                float v = C[mt][nt][i] * dd[o] + bb[o] + noise[oa];
                out[oa] = (v >= 0.f) ? v : 0.2f * v;
            }
}

// ---------------------------------------------------------------------------
extern "C" void kernel_launch(void* const* d_in, const int* in_sizes, int n_in,
                              void* d_out, int out_size) {
    const float* x     = (const float*)d_in[0];
    const float* s     = (const float*)d_in[1];
    const float* noise = (const float*)d_in[2];
    const float* w     = (const float*)d_in[3];
    const float* b     = (const float*)d_in[4];
    float* out = (float*)d_out;

    cudaFuncSetAttribute(conv_mma_kernel,
                         cudaFuncAttributeMaxDynamicSharedMemorySize, SM_DYN);

    prep_x_kernel<<<dim3(8, 64, 16), 256>>>(x, s);
    prep_w_kernel<<<(CIN * COUT + 255) / 256, 256>>>(w);
    d_kernel<<<dim3(COUT / 128, NB), 128>>>(s);
    conv_mma_kernel<<<dim3(COUT / 128, HH / 4, NB), NT, SM_DYN>>>(noise, b, out);
}